// round 1
// baseline (speedup 1.0000x reference)
#include <cuda_runtime.h>

#define OUT_DIM 11008
#define IN_DIM  4096
#define RANK    128
#define NG      32
#define NTOK    64
#define NPACK   (IN_DIM / 4)   // 1024 packed int8x4 per token

// -------- device scratch (no runtime allocation allowed) --------
__device__ float g_Wf[(size_t)OUT_DIM * IN_DIM];   // dequantized + svd-corrected W, row-major [OUT][IN]
__device__ int   g_rowmax[OUT_DIM];                // per-row max|W_f| as float bits
__device__ int   g_xq[NTOK * NPACK];               // quantized x, 4 int8 per int32
__device__ float g_scale_x[NTOK];

// -------- helpers --------
__device__ __forceinline__ unsigned long long pack2(float lo, float hi) {
    unsigned long long r;
    asm("mov.b64 %0, {%1, %2};" : "=l"(r) : "f"(lo), "f"(hi));
    return r;
}
__device__ __forceinline__ void unpack2(unsigned long long v, float& lo, float& hi) {
    asm("mov.b64 {%0, %1}, %2;" : "=f"(lo), "=f"(hi) : "l"(v));
}
// packed f32x2 FMA (Blackwell): d.lo += a.lo*b.lo ; d.hi += a.hi*b.hi  (IEEE fma per lane)
__device__ __forceinline__ void ffma2(unsigned long long& d, unsigned long long a, unsigned long long b) {
    asm("fma.rn.f32x2 %0, %1, %2, %0;" : "+l"(d) : "l"(a), "l"(b));
}
__device__ __forceinline__ int dp4a_s32(int a, int b, int c) {
    asm("dp4a.s32.s32 %0, %1, %2, %0;" : "+r"(c) : "r"(a), "r"(b));
    return c;
}
// IEEE-exact quantize of 4 floats by divisor s, round-half-even, clamp, pack to int8x4
__device__ __forceinline__ int quant_pack4(float4 v, float s) {
    int q0 = (int)fminf(fmaxf(rintf(__fdiv_rn(v.x, s)), -128.f), 127.f);
    int q1 = (int)fminf(fmaxf(rintf(__fdiv_rn(v.y, s)), -128.f), 127.f);
    int q2 = (int)fminf(fmaxf(rintf(__fdiv_rn(v.z, s)), -128.f), 127.f);
    int q3 = (int)fminf(fmaxf(rintf(__fdiv_rn(v.w, s)), -128.f), 127.f);
    return (q0 & 0xff) | ((q1 & 0xff) << 8) | ((q2 & 0xff) << 16) | (q3 << 24);
}

// ==================== kernel 1: quantize x, zero rowmax ====================
__global__ void k1_quant_x(const float* __restrict__ x) {
    __shared__ __align__(16) float s_x[IN_DIM];
    __shared__ float s_red[256];
    const int t = blockIdx.x;
    const int tid = threadIdx.x;

    // zero g_rowmax (64 blocks * 256 threads = 16384 >= 11008)
    {
        int g = t * 256 + tid;
        if (g < OUT_DIM) g_rowmax[g] = 0;
    }

    const float4* xr = reinterpret_cast<const float4*>(x + (size_t)t * IN_DIM);
    float m = 0.f;
    #pragma unroll
    for (int j = 0; j < 4; ++j) {
        int idx = tid + j * 256;
        float4 v = xr[idx];
        reinterpret_cast<float4*>(s_x)[idx] = v;
        m = fmaxf(m, fmaxf(fmaxf(fabsf(v.x), fabsf(v.y)), fmaxf(fabsf(v.z), fabsf(v.w))));
    }
    s_red[tid] = m;
    __syncthreads();
    for (int s = 128; s > 0; s >>= 1) {
        if (tid < s) s_red[tid] = fmaxf(s_red[tid], s_red[tid + s]);
        __syncthreads();
    }
    const float sx = __fdiv_rn(s_red[0], 127.0f);   // matches jnp: max/127.0
    if (tid == 0) g_scale_x[t] = sx;

    #pragma unroll
    for (int j = 0; j < 4; ++j) {
        int idx = tid + j * 256;
        float4 v = reinterpret_cast<const float4*>(s_x)[idx];
        g_xq[t * NPACK + idx] = quant_pack4(v, sx);
    }
}

// ==================== kernel 2: W_f = dequant + up@down, rowmax ====================
// grid (64 i-tiles, 172 o-tiles), 128 threads, tile 64o x 64i, K = 128 (full rank)
// thread (tx 0..7, ty 0..15): 4 rows x 8 cols, packed f32x2 accumulators
__global__ __launch_bounds__(128, 3) void k2_build_wf(
    const int*   __restrict__ weight,
    const float* __restrict__ scale,
    const float* __restrict__ zp,
    const float* __restrict__ up,
    const float* __restrict__ down)
{
    __shared__ float s_upT[RANK][65];                 // [r][o_local], padded vs conflicts
    __shared__ __align__(16) float s_down[RANK][64];  // [r][i_local]
    __shared__ int s_rmax[64];

    const int i0 = blockIdx.x * 64;
    const int o0 = blockIdx.y * 64;
    const int tid = threadIdx.x;
    const int tx = tid & 7;
    const int ty = tid >> 3;

    if (tid < 64) s_rmax[tid] = 0;

    // stage svd_up tile transposed: s_upT[r][ol] = up[(o0+ol)*128 + r]
    #pragma unroll
    for (int j = 0; j < 16; ++j) {
        int idx = tid + j * 128;
        int ol = idx >> 5, r4 = idx & 31;
        float4 v = *reinterpret_cast<const float4*>(&up[(size_t)(o0 + ol) * RANK + r4 * 4]);
        s_upT[r4 * 4 + 0][ol] = v.x;
        s_upT[r4 * 4 + 1][ol] = v.y;
        s_upT[r4 * 4 + 2][ol] = v.z;
        s_upT[r4 * 4 + 3][ol] = v.w;
    }
    // stage svd_down chunk: s_down[r][ic] = down[r*4096 + i0 + ic]
    #pragma unroll
    for (int j = 0; j < 16; ++j) {
        int idx = tid + j * 128;
        int r = idx >> 4, c4 = idx & 15;
        *reinterpret_cast<float4*>(&s_down[r][c4 * 4]) =
            *reinterpret_cast<const float4*>(&down[(size_t)r * IN_DIM + i0 + c4 * 4]);
    }
    __syncthreads();

    // init accumulators with the group-wise dequant term: (w - zp)*scale
    const int gq = i0 >> 7;   // 64-wide i tile lies in one 128-wide group
    unsigned long long acc[4][4];
    #pragma unroll
    for (int m = 0; m < 4; ++m) {
        int o = o0 + ty * 4 + m;
        float zpv = zp[o * NG + gq];
        float scv = scale[o * NG + gq];
        const int* wp = &weight[(size_t)o * IN_DIM + i0 + tx * 8];
        int4 w0 = *reinterpret_cast<const int4*>(wp);
        int4 w1 = *reinterpret_cast<const int4*>(wp + 4);
        acc[m][0] = pack2(((float)w0.x - zpv) * scv, ((float)w0.y - zpv) * scv);
        acc[m][1] = pack2(((float)w0.z - zpv) * scv, ((float)w0.w - zpv) * scv);
        acc[m][2] = pack2(((float)w1.x - zpv) * scv, ((float)w1.y - zpv) * scv);
        acc[m][3] = pack2(((float)w1.z - zpv) * scv, ((float)w1.w - zpv) * scv);
    }

    // rank-128 outer-product accumulation, FFMA2 pipe-bound
    #pragma unroll 8
    for (int r = 0; r < RANK; ++r) {
        ulonglong2 B01 = *reinterpret_cast<const ulonglong2*>(&s_down[r][tx * 8]);
        ulonglong2 B23 = *reinterpret_cast<const ulonglong2*>(&s_down[r][tx * 8 + 4]);
        #pragma unroll
        for (int m = 0; m < 4; ++m) {
            float a = s_upT[r][ty * 4 + m];
            unsigned long long A = pack2(a, a);
            ffma2(acc[m][0], A, B01.x);
            ffma2(acc[m][1], A, B01.y);
            ffma2(acc[m][2], A, B23.x);
            ffma2(acc[m][3], A, B23.y);
        }
    }

    // epilogue: row |max| + store W_f tile
    #pragma unroll
    for (int m = 0; m < 4; ++m) {
        int o = o0 + ty * 4 + m;
        float f[8];
        unpack2(acc[m][0], f[0], f[1]);
        unpack2(acc[m][1], f[2], f[3]);
        unpack2(acc[m][2], f[4], f[5]);
        unpack2(acc[m][3], f[6], f[7]);
        float lm = 0.f;
        #pragma unroll
        for (int n = 0; n < 8; ++n) lm = fmaxf(lm, fabsf(f[n]));
        atomicMax(&s_rmax[ty * 4 + m], __float_as_int(lm));   // non-negative floats: int-max == float-max
        float* op = &g_Wf[(size_t)o * IN_DIM + i0 + tx * 8];
        *reinterpret_cast<float4*>(op)     = make_float4(f[0], f[1], f[2], f[3]);
        *reinterpret_cast<float4*>(op + 4) = make_float4(f[4], f[5], f[6], f[7]);
    }
    __syncthreads();
    if (tid < 64) atomicMax(&g_rowmax[o0 + tid], s_rmax[tid]);
}

// ==================== kernel 3: quantize W rows + int8 dp4a GEMM + epilogue ====================
// grid 344 blocks (32 output rows each), 128 threads; all 64 tokens per block
// thread (tx 0..7 -> 4 o-cols, ty 0..15 -> 4 tokens); K chunk = 128 inputs (32 packs)
__global__ __launch_bounds__(128) void k3_int8_gemm(
    const float* __restrict__ bias,
    float*       __restrict__ out)
{
    __shared__ __align__(16) int s_xq[NTOK * 36];  // [t][pack], padded row 36
    __shared__ __align__(16) int s_wq[32 * 36];    // [o_local][pack]

    const int o0 = blockIdx.x * 32;
    const int tid = threadIdx.x;
    const int tx = tid & 7;
    const int ty = tid >> 3;

    int acc[4][4];
    #pragma unroll
    for (int m = 0; m < 4; ++m)
        #pragma unroll
        for (int n = 0; n < 4; ++n) acc[m][n] = 0;

    for (int c = 0; c < 32; ++c) {
        const int pc = c * 32;
        __syncthreads();
        // stage x_q chunk
        #pragma unroll
        for (int j = 0; j < 16; ++j) {
            int idx = tid + j * 128;
            int t = idx >> 5, p = idx & 31;
            s_xq[t * 36 + p] = g_xq[t * NPACK + pc + p];
        }
        // quantize W chunk on the fly (exact: round-half-even of IEEE division)
        #pragma unroll
        for (int j = 0; j < 8; ++j) {
            int idx = tid + j * 128;
            int row = idx >> 5, p = idx & 31;
            int o = o0 + row;
            float sw = __fdiv_rn(__int_as_float(g_rowmax[o]), 127.0f);
            float4 v = *reinterpret_cast<const float4*>(
                &g_Wf[(size_t)o * IN_DIM + (size_t)(pc + p) * 4]);
            s_wq[row * 36 + p] = quant_pack4(v, sw);
        }
        __syncthreads();

        #pragma unroll
        for (int p4 = 0; p4 < 8; ++p4) {
            int4 a[4], b[4];
            #pragma unroll
            for (int m = 0; m < 4; ++m)
                a[m] = *reinterpret_cast<const int4*>(&s_xq[(ty * 4 + m) * 36 + p4 * 4]);
            #pragma unroll
            for (int n = 0; n < 4; ++n)
                b[n] = *reinterpret_cast<const int4*>(&s_wq[(tx * 4 + n) * 36 + p4 * 4]);
            #pragma unroll
            for (int m = 0; m < 4; ++m)
                #pragma unroll
                for (int n = 0; n < 4; ++n) {
                    acc[m][n] = dp4a_s32(a[m].x, b[n].x, acc[m][n]);
                    acc[m][n] = dp4a_s32(a[m].y, b[n].y, acc[m][n]);
                    acc[m][n] = dp4a_s32(a[m].z, b[n].z, acc[m][n]);
                    acc[m][n] = dp4a_s32(a[m].w, b[n].w, acc[m][n]);
                }
        }
    }

    // epilogue: acc * scale_x[t] * scale_w[o] + bias[o]
    #pragma unroll
    for (int m = 0; m < 4; ++m) {
        int t = ty * 4 + m;
        float sx = g_scale_x[t];
        float rv[4];
        #pragma unroll
        for (int n = 0; n < 4; ++n) {
            int o = o0 + tx * 4 + n;
            float sw = __fdiv_rn(__int_as_float(g_rowmax[o]), 127.0f);
            rv[n] = (float)acc[m][n] * sx * sw + bias[o];
        }
        *reinterpret_cast<float4*>(&out[(size_t)t * OUT_DIM + o0 + tx * 4]) =
            make_float4(rv[0], rv[1], rv[2], rv[3]);
    }
}

// ==================== launch ====================
extern "C" void kernel_launch(void* const* d_in, const int* in_sizes, int n_in,
                              void* d_out, int out_size)
{
    const float* x      = (const float*)d_in[0];
    const int*   weight = (const int*)  d_in[1];
    const float* scale  = (const float*)d_in[2];
    const float* zp     = (const float*)d_in[3];
    const float* up     = (const float*)d_in[4];
    const float* down   = (const float*)d_in[5];
    const float* bias   = (const float*)d_in[6];
    float* out = (float*)d_out;

    k1_quant_x<<<64, 256>>>(x);
    k2_build_wf<<<dim3(64, 172), 128>>>(weight, scale, zp, up, down);
    k3_int8_gemm<<<344, 128>>>(bias, out);
}

// round 2
// speedup vs baseline: 1.4223x; 1.4223x over previous
#include <cuda_runtime.h>

#define OUT_DIM 11008
#define IN_DIM  4096
#define RANK    128
#define NG      32
#define NTOK    64
#define NPACK   (IN_DIM / 4)   // 1024 packed int8x4 per token
#define RCHUNK  16             // rank chunk staged in smem per k2 iteration

// -------- device scratch (no runtime allocation allowed) --------
__device__ float g_Wf[(size_t)OUT_DIM * IN_DIM];   // dequant + svd-corrected W, [OUT][IN]
__device__ int   g_rowmax[OUT_DIM];                // per-row max|W_f| (float bits)
__device__ float g_rcpw[OUT_DIM];                  // RN(1 / RN(rowmax/127))
__device__ int   g_xq[NTOK * NPACK];               // quantized x, int8x4
__device__ float g_scale_x[NTOK];

// -------- helpers --------
__device__ __forceinline__ unsigned long long pack2(float lo, float hi) {
    unsigned long long r;
    asm("mov.b64 %0, {%1, %2};" : "=l"(r) : "f"(lo), "f"(hi));
    return r;
}
__device__ __forceinline__ void unpack2(unsigned long long v, float& lo, float& hi) {
    asm("mov.b64 {%0, %1}, %2;" : "=f"(lo), "=f"(hi) : "l"(v));
}
// packed f32x2 FMA: d.lo += a.lo*b.lo ; d.hi += a.hi*b.hi
__device__ __forceinline__ void ffma2(unsigned long long& d, unsigned long long a, unsigned long long b) {
    asm("fma.rn.f32x2 %0, %1, %2, %0;" : "+l"(d) : "l"(a), "l"(b));
}
__device__ __forceinline__ int dp4a_s32(int a, int b, int c) {
    asm("dp4a.s32.s32 %0, %1, %2, %0;" : "+r"(c) : "r"(a), "r"(b));
    return c;
}
// exact-division quantize (used for x only: 262k divides, negligible)
__device__ __forceinline__ int quant_pack4_div(float4 v, float s) {
    int q0 = (int)fminf(fmaxf(rintf(__fdiv_rn(v.x, s)), -128.f), 127.f);
    int q1 = (int)fminf(fmaxf(rintf(__fdiv_rn(v.y, s)), -128.f), 127.f);
    int q2 = (int)fminf(fmaxf(rintf(__fdiv_rn(v.z, s)), -128.f), 127.f);
    int q3 = (int)fminf(fmaxf(rintf(__fdiv_rn(v.w, s)), -128.f), 127.f);
    return (q0 & 0xff) | ((q1 & 0xff) << 8) | ((q2 & 0xff) << 16) | (q3 << 24);
}
// multiplier quantize (W path): rcp is correctly-rounded 1/s
__device__ __forceinline__ int quant_pack4_mul(float4 v, float rcp) {
    int q0 = (int)fminf(fmaxf(rintf(v.x * rcp), -128.f), 127.f);
    int q1 = (int)fminf(fmaxf(rintf(v.y * rcp), -128.f), 127.f);
    int q2 = (int)fminf(fmaxf(rintf(v.z * rcp), -128.f), 127.f);
    int q3 = (int)fminf(fmaxf(rintf(v.w * rcp), -128.f), 127.f);
    return (q0 & 0xff) | ((q1 & 0xff) << 8) | ((q2 & 0xff) << 16) | (q3 << 24);
}

// ==================== kernel 1: quantize x, zero rowmax ====================
__global__ void k1_quant_x(const float* __restrict__ x) {
    __shared__ __align__(16) float s_x[IN_DIM];
    __shared__ float s_red[256];
    const int t = blockIdx.x;
    const int tid = threadIdx.x;

    {   // zero g_rowmax (64 * 256 = 16384 >= 11008)
        int g = t * 256 + tid;
        if (g < OUT_DIM) g_rowmax[g] = 0;
    }

    const float4* xr = reinterpret_cast<const float4*>(x + (size_t)t * IN_DIM);
    float m = 0.f;
    #pragma unroll
    for (int j = 0; j < 4; ++j) {
        int idx = tid + j * 256;
        float4 v = xr[idx];
        reinterpret_cast<float4*>(s_x)[idx] = v;
        m = fmaxf(m, fmaxf(fmaxf(fabsf(v.x), fabsf(v.y)), fmaxf(fabsf(v.z), fabsf(v.w))));
    }
    s_red[tid] = m;
    __syncthreads();
    for (int s = 128; s > 0; s >>= 1) {
        if (tid < s) s_red[tid] = fmaxf(s_red[tid], s_red[tid + s]);
        __syncthreads();
    }
    const float sx = __fdiv_rn(s_red[0], 127.0f);
    if (tid == 0) g_scale_x[t] = sx;

    #pragma unroll
    for (int j = 0; j < 4; ++j) {
        int idx = tid + j * 256;
        float4 v = reinterpret_cast<const float4*>(s_x)[idx];
        g_xq[t * NPACK + idx] = quant_pack4_div(v, sx);
    }
}

// ==================== kernel 2: W_f = dequant + up@down, rowmax ====================
// grid (32 i-tiles, 86 o-tiles), 256 threads, tile 128o x 128i
// thread (tx 0..15 -> 8 i-cols, ty 0..15 -> 8 o-rows); pure-FFMA2 inner loop
__global__ __launch_bounds__(256, 2) void k2_build_wf(
    const int*   __restrict__ weight,
    const float* __restrict__ scale,
    const float* __restrict__ zp,
    const float* __restrict__ up,
    const float* __restrict__ down)
{
    __shared__ __align__(16) float2 s_up2[RCHUNK][128];   // dup pairs {a,a}, 16KB
    __shared__ __align__(16) float  s_down[RCHUNK][128];  // 8KB
    __shared__ int s_rmax[128];

    const int i0 = blockIdx.x * 128;
    const int o0 = blockIdx.y * 128;
    const int tid = threadIdx.x;
    const int tx = tid & 15;
    const int ty = tid >> 4;

    if (tid < 128) s_rmax[tid] = 0;

    // init accumulators with group-wise dequant: (w - zp)*scale  (one group per i-tile)
    const int gq = blockIdx.x;   // i0 / 128
    unsigned long long acc[8][4];
    #pragma unroll
    for (int m = 0; m < 8; ++m) {
        const int o = o0 + ty * 8 + m;
        const float zpv = zp[o * NG + gq];
        const float scv = scale[o * NG + gq];
        const int* wp = &weight[(size_t)o * IN_DIM + i0 + tx * 8];
        int4 w0 = *reinterpret_cast<const int4*>(wp);
        int4 w1 = *reinterpret_cast<const int4*>(wp + 4);
        acc[m][0] = pack2(((float)w0.x - zpv) * scv, ((float)w0.y - zpv) * scv);
        acc[m][1] = pack2(((float)w0.z - zpv) * scv, ((float)w0.w - zpv) * scv);
        acc[m][2] = pack2(((float)w1.x - zpv) * scv, ((float)w1.y - zpv) * scv);
        acc[m][3] = pack2(((float)w1.z - zpv) * scv, ((float)w1.w - zpv) * scv);
    }

    // rank loop in chunks of RCHUNK
    for (int c = 0; c < RANK / RCHUNK; ++c) {
        __syncthreads();
        // stage up chunk as duplicated pairs: s_up2[r][ol] = {a,a}
        {
            const int ol = tid >> 1;
            const int rq = (tid & 1) * 8;
            const float* upp = &up[(size_t)(o0 + ol) * RANK + c * RCHUNK + rq];
            #pragma unroll
            for (int k = 0; k < 2; ++k) {
                float4 v = *reinterpret_cast<const float4*>(upp + k * 4);
                s_up2[rq + k * 4 + 0][ol] = make_float2(v.x, v.x);
                s_up2[rq + k * 4 + 1][ol] = make_float2(v.y, v.y);
                s_up2[rq + k * 4 + 2][ol] = make_float2(v.z, v.z);
                s_up2[rq + k * 4 + 3][ol] = make_float2(v.w, v.w);
            }
        }
        // stage down chunk
        {
            const int r = tid >> 4;
            const int seg = (tid & 15) * 8;
            const float* dp = &down[(size_t)(c * RCHUNK + r) * IN_DIM + i0 + seg];
            *reinterpret_cast<float4*>(&s_down[r][seg])     = *reinterpret_cast<const float4*>(dp);
            *reinterpret_cast<float4*>(&s_down[r][seg + 4]) = *reinterpret_cast<const float4*>(dp + 4);
        }
        __syncthreads();

        #pragma unroll
        for (int r = 0; r < RCHUNK; ++r) {
            const ulonglong2* Ap = reinterpret_cast<const ulonglong2*>(&s_up2[r][ty * 8]);
            const ulonglong2* Bp = reinterpret_cast<const ulonglong2*>(&s_down[r][tx * 8]);
            ulonglong2 A0 = Ap[0], A1 = Ap[1], A2 = Ap[2], A3 = Ap[3];
            ulonglong2 B0 = Bp[0], B1 = Bp[1];
            ffma2(acc[0][0], A0.x, B0.x); ffma2(acc[0][1], A0.x, B0.y);
            ffma2(acc[0][2], A0.x, B1.x); ffma2(acc[0][3], A0.x, B1.y);
            ffma2(acc[1][0], A0.y, B0.x); ffma2(acc[1][1], A0.y, B0.y);
            ffma2(acc[1][2], A0.y, B1.x); ffma2(acc[1][3], A0.y, B1.y);
            ffma2(acc[2][0], A1.x, B0.x); ffma2(acc[2][1], A1.x, B0.y);
            ffma2(acc[2][2], A1.x, B1.x); ffma2(acc[2][3], A1.x, B1.y);
            ffma2(acc[3][0], A1.y, B0.x); ffma2(acc[3][1], A1.y, B0.y);
            ffma2(acc[3][2], A1.y, B1.x); ffma2(acc[3][3], A1.y, B1.y);
            ffma2(acc[4][0], A2.x, B0.x); ffma2(acc[4][1], A2.x, B0.y);
            ffma2(acc[4][2], A2.x, B1.x); ffma2(acc[4][3], A2.x, B1.y);
            ffma2(acc[5][0], A2.y, B0.x); ffma2(acc[5][1], A2.y, B0.y);
            ffma2(acc[5][2], A2.y, B1.x); ffma2(acc[5][3], A2.y, B1.y);
            ffma2(acc[6][0], A3.x, B0.x); ffma2(acc[6][1], A3.x, B0.y);
            ffma2(acc[6][2], A3.x, B1.x); ffma2(acc[6][3], A3.x, B1.y);
            ffma2(acc[7][0], A3.y, B0.x); ffma2(acc[7][1], A3.y, B0.y);
            ffma2(acc[7][2], A3.y, B1.x); ffma2(acc[7][3], A3.y, B1.y);
        }
    }

    // epilogue: per-row |max| + store W_f
    #pragma unroll
    for (int m = 0; m < 8; ++m) {
        const int o = o0 + ty * 8 + m;
        float f[8];
        unpack2(acc[m][0], f[0], f[1]);
        unpack2(acc[m][1], f[2], f[3]);
        unpack2(acc[m][2], f[4], f[5]);
        unpack2(acc[m][3], f[6], f[7]);
        float lm = 0.f;
        #pragma unroll
        for (int n = 0; n < 8; ++n) lm = fmaxf(lm, fabsf(f[n]));
        atomicMax(&s_rmax[ty * 8 + m], __float_as_int(lm));
        float* op = &g_Wf[(size_t)o * IN_DIM + i0 + tx * 8];
        *reinterpret_cast<float4*>(op)     = make_float4(f[0], f[1], f[2], f[3]);
        *reinterpret_cast<float4*>(op + 4) = make_float4(f[4], f[5], f[6], f[7]);
    }
    __syncthreads();
    if (tid < 128) atomicMax(&g_rowmax[o0 + tid], s_rmax[tid]);
}

// ==================== kernel 2b: per-row quant multiplier ====================
__global__ void k2b_rowrcp() {
    int o = blockIdx.x * 256 + threadIdx.x;
    if (o < OUT_DIM) {
        float s = __fdiv_rn(__int_as_float(g_rowmax[o]), 127.0f);
        g_rcpw[o] = __frcp_rn(s);
    }
}

// ==================== kernel 3: quantize W rows + int8 dp4a GEMM + epilogue ====================
__global__ __launch_bounds__(128) void k3_int8_gemm(
    const float* __restrict__ bias,
    float*       __restrict__ out)
{
    __shared__ __align__(16) int s_xq[NTOK * 36];  // [t][pack], padded
    __shared__ __align__(16) int s_wq[32 * 36];    // [o_local][pack]

    const int o0 = blockIdx.x * 32;
    const int tid = threadIdx.x;
    const int tx = tid & 7;
    const int ty = tid >> 3;

    // preload this thread's 8 quant multipliers (rows (tid>>5)+4j)
    float rcp8[8];
    #pragma unroll
    for (int j = 0; j < 8; ++j) rcp8[j] = g_rcpw[o0 + (tid >> 5) + j * 4];

    int acc[4][4];
    #pragma unroll
    for (int m = 0; m < 4; ++m)
        #pragma unroll
        for (int n = 0; n < 4; ++n) acc[m][n] = 0;

    for (int c = 0; c < 32; ++c) {
        const int pc = c * 32;
        __syncthreads();
        #pragma unroll
        for (int j = 0; j < 16; ++j) {
            int idx = tid + j * 128;
            int t = idx >> 5, p = idx & 31;
            s_xq[t * 36 + p] = g_xq[t * NPACK + pc + p];
        }
        #pragma unroll
        for (int j = 0; j < 8; ++j) {
            int idx = tid + j * 128;
            int row = idx >> 5, p = idx & 31;
            float4 v = *reinterpret_cast<const float4*>(
                &g_Wf[(size_t)(o0 + row) * IN_DIM + (size_t)(pc + p) * 4]);
            s_wq[row * 36 + p] = quant_pack4_mul(v, rcp8[j]);
        }
        __syncthreads();

        #pragma unroll
        for (int p4 = 0; p4 < 8; ++p4) {
            int4 a[4], b[4];
            #pragma unroll
            for (int m = 0; m < 4; ++m)
                a[m] = *reinterpret_cast<const int4*>(&s_xq[(ty * 4 + m) * 36 + p4 * 4]);
            #pragma unroll
            for (int n = 0; n < 4; ++n)
                b[n] = *reinterpret_cast<const int4*>(&s_wq[(tx * 4 + n) * 36 + p4 * 4]);
            #pragma unroll
            for (int m = 0; m < 4; ++m)
                #pragma unroll
                for (int n = 0; n < 4; ++n) {
                    acc[m][n] = dp4a_s32(a[m].x, b[n].x, acc[m][n]);
                    acc[m][n] = dp4a_s32(a[m].y, b[n].y, acc[m][n]);
                    acc[m][n] = dp4a_s32(a[m].z, b[n].z, acc[m][n]);
                    acc[m][n] = dp4a_s32(a[m].w, b[n].w, acc[m][n]);
                }
        }
    }

    // epilogue
    #pragma unroll
    for (int m = 0; m < 4; ++m) {
        int t = ty * 4 + m;
        float sx = g_scale_x[t];
        float rv[4];
        #pragma unroll
        for (int n = 0; n < 4; ++n) {
            int o = o0 + tx * 4 + n;
            float sw = __fdiv_rn(__int_as_float(g_rowmax[o]), 127.0f);
            rv[n] = (float)acc[m][n] * sx * sw + bias[o];
        }
        *reinterpret_cast<float4*>(&out[(size_t)t * OUT_DIM + o0 + tx * 4]) =
            make_float4(rv[0], rv[1], rv[2], rv[3]);
    }
}

// ==================== launch ====================
extern "C" void kernel_launch(void* const* d_in, const int* in_sizes, int n_in,
                              void* d_out, int out_size)
{
    const float* x      = (const float*)d_in[0];
    const int*   weight = (const int*)  d_in[1];
    const float* scale  = (const float*)d_in[2];
    const float* zp     = (const float*)d_in[3];
    const float* up     = (const float*)d_in[4];
    const float* down   = (const float*)d_in[5];
    const float* bias   = (const float*)d_in[6];
    float* out = (float*)d_out;

    k1_quant_x<<<64, 256>>>(x);
    k2_build_wf<<<dim3(32, 86), 256>>>(weight, scale, zp, up, down);
    k2b_rowrcp<<<(OUT_DIM + 255) / 256, 256>>>();
    k3_int8_gemm<<<344, 128>>>(bias, out);
}

// round 4
// speedup vs baseline: 1.8007x; 1.2660x over previous
#include <cuda_runtime.h>
#include <cuda_bf16.h>
#include <cstdint>

#define OUT_DIM 11008
#define IN_DIM  4096
#define RANK    128
#define NG      32
#define NTOK    64
#define NPACK   1024

// -------- device scratch --------
__device__ float g_Wf[(size_t)OUT_DIM * IN_DIM];
__device__ int   g_rowmax[OUT_DIM];
__device__ float g_rcpw[OUT_DIM];
__device__ int   g_xq[NTOK * NPACK];
__device__ float g_scale_x[NTOK];
__device__ __nv_bfloat16 g_up_hi[(size_t)OUT_DIM * RANK];
__device__ __nv_bfloat16 g_up_lo[(size_t)OUT_DIM * RANK];
__device__ __nv_bfloat16 g_dT_hi[(size_t)IN_DIM * RANK];
__device__ __nv_bfloat16 g_dT_lo[(size_t)IN_DIM * RANK];
__device__ int   g_part[4][NTOK * OUT_DIM];

// -------- warp MMA helpers (base-target legal: sm_80+) --------
__device__ __forceinline__ uint32_t smem_to_u32(const void* p) {
    uint32_t a;
    asm("{ .reg .u64 t; cvta.to.shared.u64 t, %1; cvt.u32.u64 %0, t; }" : "=r"(a) : "l"(p));
    return a;
}
__device__ __forceinline__ void ldsm_x4(uint32_t (&r)[4], uint32_t addr) {
    asm volatile("ldmatrix.sync.aligned.m8n8.x4.shared.b16 {%0,%1,%2,%3}, [%4];"
        : "=r"(r[0]), "=r"(r[1]), "=r"(r[2]), "=r"(r[3]) : "r"(addr));
}
__device__ __forceinline__ void mma_bf16(float (&c)[4], const uint32_t (&a)[4],
                                         uint32_t b0, uint32_t b1) {
    asm volatile("mma.sync.aligned.m16n8k16.row.col.f32.bf16.bf16.f32 "
        "{%0,%1,%2,%3}, {%4,%5,%6,%7}, {%8,%9}, {%0,%1,%2,%3};"
        : "+f"(c[0]), "+f"(c[1]), "+f"(c[2]), "+f"(c[3])
        : "r"(a[0]), "r"(a[1]), "r"(a[2]), "r"(a[3]), "r"(b0), "r"(b1));
}
__device__ __forceinline__ int dp4a_s32(int a, int b, int c) {
    asm("dp4a.s32.s32 %0, %1, %2, %0;" : "+r"(c) : "r"(a), "r"(b));
    return c;
}
// swizzle for 256B-pitch rows: XOR 16B-chunk index by row%8 (self-inverse)
__device__ __forceinline__ uint32_t swz(uint32_t b) { return b ^ (((b >> 8) & 7u) << 4); }

// quantize 4 floats by multiplier rcp (|v*rcp| <= 127*(1+eps) < 127.5: no clamp needed)
__device__ __forceinline__ int quant_pack4_mul(float4 v, float rcp) {
    int q0 = __float2int_rn(v.x * rcp);
    int q1 = __float2int_rn(v.y * rcp);
    int q2 = __float2int_rn(v.z * rcp);
    int q3 = __float2int_rn(v.w * rcp);
    return (q0 & 0xff) | ((q1 & 0xff) << 8) | ((q2 & 0xff) << 16) | (q3 << 24);
}

// ==================== k1: quantize x, zero rowmax ====================
__global__ void k1_quant_x(const float* __restrict__ x) {
    __shared__ __align__(16) float s_x[IN_DIM];
    __shared__ float s_red[256];
    const int t = blockIdx.x;
    const int tid = threadIdx.x;
    {
        int g = t * 256 + tid;
        if (g < OUT_DIM) g_rowmax[g] = 0;
    }
    const float4* xr = reinterpret_cast<const float4*>(x + (size_t)t * IN_DIM);
    float m = 0.f;
    #pragma unroll
    for (int j = 0; j < 4; ++j) {
        int idx = tid + j * 256;
        float4 v = xr[idx];
        reinterpret_cast<float4*>(s_x)[idx] = v;
        m = fmaxf(m, fmaxf(fmaxf(fabsf(v.x), fabsf(v.y)), fmaxf(fabsf(v.z), fabsf(v.w))));
    }
    s_red[tid] = m;
    __syncthreads();
    for (int s = 128; s > 0; s >>= 1) {
        if (tid < s) s_red[tid] = fmaxf(s_red[tid], s_red[tid + s]);
        __syncthreads();
    }
    const float sx = __fdiv_rn(s_red[0], 127.0f);
    if (tid == 0) g_scale_x[t] = sx;
    #pragma unroll
    for (int j = 0; j < 4; ++j) {
        int idx = tid + j * 256;
        float4 v = reinterpret_cast<const float4*>(s_x)[idx];
        int q0 = __float2int_rn(__fdiv_rn(v.x, sx));
        int q1 = __float2int_rn(__fdiv_rn(v.y, sx));
        int q2 = __float2int_rn(__fdiv_rn(v.z, sx));
        int q3 = __float2int_rn(__fdiv_rn(v.w, sx));
        g_xq[t * NPACK + idx] = (q0 & 0xff) | ((q1 & 0xff) << 8) | ((q2 & 0xff) << 16) | (q3 << 24);
    }
}

// ==================== prep: bf16 two-term splits ====================
__global__ void kp_split_up(const float* __restrict__ up) {
    int idx = blockIdx.x * 256 + threadIdx.x;
    if (idx < OUT_DIM * RANK / 4) {
        float4 v = reinterpret_cast<const float4*>(up)[idx];
        float f[4] = {v.x, v.y, v.z, v.w};
        uint32_t hi[2], lo[2];
        #pragma unroll
        for (int k = 0; k < 2; ++k) {
            __nv_bfloat16 h0 = __float2bfloat16(f[k*2+0]);
            __nv_bfloat16 h1 = __float2bfloat16(f[k*2+1]);
            __nv_bfloat16 l0 = __float2bfloat16(f[k*2+0] - __bfloat162float(h0));
            __nv_bfloat16 l1 = __float2bfloat16(f[k*2+1] - __bfloat162float(h1));
            hi[k] = (uint32_t)__bfloat16_as_ushort(h0) | ((uint32_t)__bfloat16_as_ushort(h1) << 16);
            lo[k] = (uint32_t)__bfloat16_as_ushort(l0) | ((uint32_t)__bfloat16_as_ushort(l1) << 16);
        }
        reinterpret_cast<uint2*>(g_up_hi)[idx] = make_uint2(hi[0], hi[1]);
        reinterpret_cast<uint2*>(g_up_lo)[idx] = make_uint2(lo[0], lo[1]);
    }
}

__global__ void kp_split_downT(const float* __restrict__ down) {
    __shared__ float t[32][33];
    const int bx = blockIdx.x, by = blockIdx.y;
    const int tx = threadIdx.x, ty = threadIdx.y;
    #pragma unroll
    for (int k = 0; k < 4; ++k)
        t[ty + k * 8][tx] = down[(size_t)(by * 32 + ty + k * 8) * IN_DIM + bx * 32 + tx];
    __syncthreads();
    #pragma unroll
    for (int k = 0; k < 4; ++k) {
        int i = bx * 32 + ty + k * 8;
        int r = by * 32 + tx;
        float v = t[tx][ty + k * 8];
        __nv_bfloat16 h = __float2bfloat16(v);
        __nv_bfloat16 l = __float2bfloat16(v - __bfloat162float(h));
        g_dT_hi[(size_t)i * RANK + r] = h;
        g_dT_lo[(size_t)i * RANK + r] = l;
    }
}

// ==================== k2: mma.sync bf16 split GEMM + fused epilogue ====================
// grid(64 i-tiles[N=64], 86 o-tiles[M=128]), 256 threads = 8 warps (4m x 2n).
// D = up_hi*dT_hi + up_lo*dT_hi + up_hi*dT_lo (3 passes, K=128).
// Epilogue in registers: W_f = (w - zp)*scale + D, rowmax, store.
#define OFF_AH 0
#define OFF_AL 32768
#define OFF_BH 65536
#define OFF_BL 81920
#define K2_SMEM 98304

__global__ __launch_bounds__(256, 2) void k2_mma(
    const int* __restrict__ weight,
    const float* __restrict__ scale,
    const float* __restrict__ zp)
{
    extern __shared__ __align__(1024) char smem[];
    __shared__ int s_rmax[128];
    const uint32_t sb = smem_to_u32(smem);
    const int tid = threadIdx.x;
    const int wid = tid >> 5;
    const int lane = tid & 31;
    const int i0 = blockIdx.x * 64;
    const int o0 = blockIdx.y * 128;

    if (tid < 128) s_rmax[tid] = 0;

    // ---- stage A (up o-tile, hi+lo): 128 rows x 256B, swizzled ----
    #pragma unroll
    for (int j = 0; j < 8; ++j) {
        int idx = tid + j * 256;
        int row = idx >> 4;
        int ch = idx & 15;
        uint32_t dst = swz((uint32_t)(row * 256 + ch * 16));
        size_t src = (size_t)(o0 + row) * 256 + ch * 16;
        *reinterpret_cast<uint4*>(smem + OFF_AH + dst) =
            *reinterpret_cast<const uint4*>(reinterpret_cast<const char*>(g_up_hi) + src);
        *reinterpret_cast<uint4*>(smem + OFF_AL + dst) =
            *reinterpret_cast<const uint4*>(reinterpret_cast<const char*>(g_up_lo) + src);
    }
    // ---- stage B (downT i-tile, hi+lo): 64 rows x 256B ----
    #pragma unroll
    for (int j = 0; j < 4; ++j) {
        int idx = tid + j * 256;
        int row = idx >> 4;
        int ch = idx & 15;
        uint32_t dst = swz((uint32_t)(row * 256 + ch * 16));
        size_t src = (size_t)(i0 + row) * 256 + ch * 16;
        *reinterpret_cast<uint4*>(smem + OFF_BH + dst) =
            *reinterpret_cast<const uint4*>(reinterpret_cast<const char*>(g_dT_hi) + src);
        *reinterpret_cast<uint4*>(smem + OFF_BL + dst) =
            *reinterpret_cast<const uint4*>(reinterpret_cast<const char*>(g_dT_lo) + src);
    }
    __syncthreads();

    const int wm = (wid & 3) * 32;   // warp m-base (o rows)
    const int wn = (wid >> 2) * 32;  // warp n-base (i cols)

    float c[2][4][4];
    #pragma unroll
    for (int mi = 0; mi < 2; ++mi)
        #pragma unroll
        for (int ni = 0; ni < 4; ++ni)
            #pragma unroll
            for (int q = 0; q < 4; ++q) c[mi][ni][q] = 0.f;

    // A-frag ldmatrix address pieces
    const int a_row = (lane & 15);
    const int a_ch  = (lane >> 4);
    // B-frag (x4 over two n-tiles) pieces
    const int b_row = (lane & 7) + ((lane >> 4) << 3);
    const int b_ch  = (lane >> 3) & 1;

    #pragma unroll
    for (int pass = 0; pass < 3; ++pass) {
        const uint32_t Aoff = sb + ((pass == 1) ? OFF_AL : OFF_AH);
        const uint32_t Boff = sb + ((pass == 2) ? OFF_BL : OFF_BH);
        #pragma unroll
        for (int ks = 0; ks < 8; ++ks) {
            uint32_t a[2][4], b[2][4];
            #pragma unroll
            for (int mi = 0; mi < 2; ++mi)
                ldsm_x4(a[mi], Aoff + swz((uint32_t)((wm + mi * 16 + a_row) * 256
                                                     + (ks * 2 + a_ch) * 16)));
            #pragma unroll
            for (int g = 0; g < 2; ++g)
                ldsm_x4(b[g], Boff + swz((uint32_t)((wn + g * 16 + b_row) * 256
                                                    + (ks * 2 + b_ch) * 16)));
            #pragma unroll
            for (int mi = 0; mi < 2; ++mi)
                #pragma unroll
                for (int ni = 0; ni < 4; ++ni)
                    mma_bf16(c[mi][ni], a[mi], b[ni >> 1][(ni & 1) * 2], b[ni >> 1][(ni & 1) * 2 + 1]);
        }
    }

    // ---- fused epilogue ----
    const int gq = blockIdx.x >> 1;   // 64-wide i-tile -> 128-wide quant group
    #pragma unroll
    for (int mi = 0; mi < 2; ++mi) {
        #pragma unroll
        for (int half = 0; half < 2; ++half) {
            const int rloc = wm + mi * 16 + (lane >> 2) + half * 8;
            const int o = o0 + rloc;
            const float zpv = zp[o * NG + gq];
            const float scv = scale[o * NG + gq];
            float mx = 0.f;
            #pragma unroll
            for (int ni = 0; ni < 4; ++ni) {
                const int i = i0 + wn + ni * 8 + (lane & 3) * 2;
                int2 w = *reinterpret_cast<const int2*>(&weight[(size_t)o * IN_DIM + i]);
                float v0 = fmaf((float)w.x - zpv, scv, c[mi][ni][half * 2 + 0]);
                float v1 = fmaf((float)w.y - zpv, scv, c[mi][ni][half * 2 + 1]);
                mx = fmaxf(mx, fmaxf(fabsf(v0), fabsf(v1)));
                *reinterpret_cast<float2*>(&g_Wf[(size_t)o * IN_DIM + i]) = make_float2(v0, v1);
            }
            atomicMax(&s_rmax[rloc], __float_as_int(mx));
        }
    }
    __syncthreads();
    if (tid < 128) atomicMax(&g_rowmax[o0 + tid], s_rmax[tid]);
}

// ==================== k2b: per-row quant multiplier ====================
__global__ void k2b_rowrcp() {
    int o = blockIdx.x * 256 + threadIdx.x;
    if (o < OUT_DIM) {
        float s = __fdiv_rn(__int_as_float(g_rowmax[o]), 127.0f);
        g_rcpw[o] = __frcp_rn(s);
    }
}

// ==================== k3: W quant + dp4a GEMM (K-split x4) ====================
// grid(86 o-tiles[128], 4 k-slices[1024 in]), 256 threads
__global__ __launch_bounds__(256) void k3_int8() {
    __shared__ __align__(16) int s_xq[NTOK * 36];
    __shared__ __align__(16) int s_wq[128 * 36];
    __shared__ float s_rcp[128];
    const int o0 = blockIdx.x * 128;
    const int kb = blockIdx.y;
    const int tid = threadIdx.x;
    const int tx = tid & 15;
    const int ty = tid >> 4;
    if (tid < 128) s_rcp[tid] = g_rcpw[o0 + tid];

    int acc[4][8];
    #pragma unroll
    for (int m = 0; m < 4; ++m)
        #pragma unroll
        for (int n = 0; n < 8; ++n) acc[m][n] = 0;

    const int pb = kb * 256;
    for (int c = 0; c < 8; ++c) {
        const int pc = pb + c * 32;
        __syncthreads();
        #pragma unroll
        for (int j = 0; j < 8; ++j) {
            int idx = tid + j * 256;
            int t = idx >> 5, p = idx & 31;
            s_xq[t * 36 + p] = g_xq[t * NPACK + pc + p];
        }
        #pragma unroll
        for (int j = 0; j < 16; ++j) {
            int idx = tid + j * 256;
            int row = idx >> 5, p = idx & 31;
            float4 v = *reinterpret_cast<const float4*>(
                &g_Wf[(size_t)(o0 + row) * IN_DIM + (size_t)(pc + p) * 4]);
            s_wq[row * 36 + p] = quant_pack4_mul(v, s_rcp[row]);
        }
        __syncthreads();

        #pragma unroll
        for (int p4 = 0; p4 < 8; ++p4) {
            int4 a[4];
            #pragma unroll
            for (int m = 0; m < 4; ++m)
                a[m] = *reinterpret_cast<const int4*>(&s_xq[(ty + 16 * m) * 36 + p4 * 4]);
            #pragma unroll
            for (int n = 0; n < 8; ++n) {
                int4 b = *reinterpret_cast<const int4*>(&s_wq[(tx + 16 * n) * 36 + p4 * 4]);
                #pragma unroll
                for (int m = 0; m < 4; ++m) {
                    acc[m][n] = dp4a_s32(a[m].x, b.x, acc[m][n]);
                    acc[m][n] = dp4a_s32(a[m].y, b.y, acc[m][n]);
                    acc[m][n] = dp4a_s32(a[m].z, b.z, acc[m][n]);
                    acc[m][n] = dp4a_s32(a[m].w, b.w, acc[m][n]);
                }
            }
        }
    }

    #pragma unroll
    for (int m = 0; m < 4; ++m) {
        int t = ty + 16 * m;
        #pragma unroll
        for (int n = 0; n < 8; ++n)
            g_part[kb][t * OUT_DIM + o0 + tx + 16 * n] = acc[m][n];
    }
}

// ==================== k4: combine partials + epilogue ====================
__global__ void k4_out(const float* __restrict__ bias, float* __restrict__ out) {
    int o = blockIdx.x * 256 + threadIdx.x;
    int t = blockIdx.y;
    if (o < OUT_DIM) {
        int s = g_part[0][t * OUT_DIM + o] + g_part[1][t * OUT_DIM + o]
              + g_part[2][t * OUT_DIM + o] + g_part[3][t * OUT_DIM + o];
        float sw = __fdiv_rn(__int_as_float(g_rowmax[o]), 127.0f);
        out[(size_t)t * OUT_DIM + o] = ((float)s * g_scale_x[t]) * sw + bias[o];
    }
}

// ==================== launch ====================
extern "C" void kernel_launch(void* const* d_in, const int* in_sizes, int n_in,
                              void* d_out, int out_size)
{
    const float* x      = (const float*)d_in[0];
    const int*   weight = (const int*)  d_in[1];
    const float* scale  = (const float*)d_in[2];
    const float* zp     = (const float*)d_in[3];
    const float* up     = (const float*)d_in[4];
    const float* down   = (const float*)d_in[5];
    const float* bias   = (const float*)d_in[6];
    float* out = (float*)d_out;

    static int attr_set = 0;
    if (!attr_set) {
        cudaFuncSetAttribute(k2_mma, cudaFuncAttributeMaxDynamicSharedMemorySize, K2_SMEM);
        attr_set = 1;
    }

    k1_quant_x<<<64, 256>>>(x);
    kp_split_up<<<(OUT_DIM * RANK / 4 + 255) / 256, 256>>>(up);
    kp_split_downT<<<dim3(IN_DIM / 32, RANK / 32), dim3(32, 8)>>>(down);
    k2_mma<<<dim3(64, 86), 256, K2_SMEM>>>(weight, scale, zp);
    k2b_rowrcp<<<(OUT_DIM + 255) / 256, 256>>>();
    k3_int8<<<dim3(86, 4), 256>>>();
    k4_out<<<dim3((OUT_DIM + 255) / 256, NTOK), 256>>>(bias, out);
}

// round 5
// speedup vs baseline: 2.4123x; 1.3397x over previous
#include <cuda_runtime.h>
#include <cuda_bf16.h>
#include <cstdint>

#define OUT_DIM 11008
#define IN_DIM  4096
#define RANK    128
#define NG      32
#define NTOK    64
#define NPACK   1024

// -------- device scratch --------
__device__ float g_Wf[(size_t)OUT_DIM * IN_DIM];
__device__ int   g_rowmax[OUT_DIM];
__device__ float g_rcpw[OUT_DIM];
__device__ int   g_xq[NTOK * NPACK];
__device__ float g_scale_x[NTOK];
__device__ __nv_bfloat16 g_up_hi[(size_t)OUT_DIM * RANK];
__device__ __nv_bfloat16 g_up_lo[(size_t)OUT_DIM * RANK];
__device__ __nv_bfloat16 g_dT_hi[(size_t)IN_DIM * RANK];
__device__ __nv_bfloat16 g_dT_lo[(size_t)IN_DIM * RANK];
__device__ int   g_part[4][NTOK * OUT_DIM];

// -------- warp MMA helpers --------
__device__ __forceinline__ uint32_t smem_to_u32(const void* p) {
    uint32_t a;
    asm("{ .reg .u64 t; cvta.to.shared.u64 t, %1; cvt.u32.u64 %0, t; }" : "=r"(a) : "l"(p));
    return a;
}
__device__ __forceinline__ void ldsm_x4(uint32_t (&r)[4], uint32_t addr) {
    asm volatile("ldmatrix.sync.aligned.m8n8.x4.shared.b16 {%0,%1,%2,%3}, [%4];"
        : "=r"(r[0]), "=r"(r[1]), "=r"(r[2]), "=r"(r[3]) : "r"(addr));
}
__device__ __forceinline__ void mma_bf16(float (&c)[4], const uint32_t (&a)[4],
                                         uint32_t b0, uint32_t b1) {
    asm volatile("mma.sync.aligned.m16n8k16.row.col.f32.bf16.bf16.f32 "
        "{%0,%1,%2,%3}, {%4,%5,%6,%7}, {%8,%9}, {%0,%1,%2,%3};"
        : "+f"(c[0]), "+f"(c[1]), "+f"(c[2]), "+f"(c[3])
        : "r"(a[0]), "r"(a[1]), "r"(a[2]), "r"(a[3]), "r"(b0), "r"(b1));
}
__device__ __forceinline__ int dp4a_s32(int a, int b, int c) {
    asm("dp4a.s32.s32 %0, %1, %2, %0;" : "+r"(c) : "r"(a), "r"(b));
    return c;
}
// swizzle for 256B-pitch rows: XOR 16B-chunk index by row%8 (self-inverse)
__device__ __forceinline__ uint32_t swz(uint32_t b) { return b ^ (((b >> 8) & 7u) << 4); }

__device__ __forceinline__ int quant_pack4_mul(float4 v, float rcp) {
    int q0 = __float2int_rn(v.x * rcp);
    int q1 = __float2int_rn(v.y * rcp);
    int q2 = __float2int_rn(v.z * rcp);
    int q3 = __float2int_rn(v.w * rcp);
    return (q0 & 0xff) | ((q1 & 0xff) << 8) | ((q2 & 0xff) << 16) | (q3 << 24);
}

// ==================== k1: quantize x, zero rowmax ====================
__global__ void k1_quant_x(const float* __restrict__ x) {
    __shared__ __align__(16) float s_x[IN_DIM];
    __shared__ float s_red[256];
    const int t = blockIdx.x;
    const int tid = threadIdx.x;
    {
        int g = t * 256 + tid;
        if (g < OUT_DIM) g_rowmax[g] = 0;
    }
    const float4* xr = reinterpret_cast<const float4*>(x + (size_t)t * IN_DIM);
    float m = 0.f;
    #pragma unroll
    for (int j = 0; j < 4; ++j) {
        int idx = tid + j * 256;
        float4 v = xr[idx];
        reinterpret_cast<float4*>(s_x)[idx] = v;
        m = fmaxf(m, fmaxf(fmaxf(fabsf(v.x), fabsf(v.y)), fmaxf(fabsf(v.z), fabsf(v.w))));
    }
    s_red[tid] = m;
    __syncthreads();
    for (int s = 128; s > 0; s >>= 1) {
        if (tid < s) s_red[tid] = fmaxf(s_red[tid], s_red[tid + s]);
        __syncthreads();
    }
    const float sx = __fdiv_rn(s_red[0], 127.0f);
    if (tid == 0) g_scale_x[t] = sx;
    #pragma unroll
    for (int j = 0; j < 4; ++j) {
        int idx = tid + j * 256;
        float4 v = reinterpret_cast<const float4*>(s_x)[idx];
        int q0 = __float2int_rn(__fdiv_rn(v.x, sx));
        int q1 = __float2int_rn(__fdiv_rn(v.y, sx));
        int q2 = __float2int_rn(__fdiv_rn(v.z, sx));
        int q3 = __float2int_rn(__fdiv_rn(v.w, sx));
        g_xq[t * NPACK + idx] = (q0 & 0xff) | ((q1 & 0xff) << 8) | ((q2 & 0xff) << 16) | (q3 << 24);
    }
}

// ==================== prep: bf16 two-term splits ====================
__global__ void kp_split_up(const float* __restrict__ up) {
    int idx = blockIdx.x * 256 + threadIdx.x;
    if (idx < OUT_DIM * RANK / 4) {
        float4 v = reinterpret_cast<const float4*>(up)[idx];
        float f[4] = {v.x, v.y, v.z, v.w};
        uint32_t hi[2], lo[2];
        #pragma unroll
        for (int k = 0; k < 2; ++k) {
            __nv_bfloat16 h0 = __float2bfloat16(f[k*2+0]);
            __nv_bfloat16 h1 = __float2bfloat16(f[k*2+1]);
            __nv_bfloat16 l0 = __float2bfloat16(f[k*2+0] - __bfloat162float(h0));
            __nv_bfloat16 l1 = __float2bfloat16(f[k*2+1] - __bfloat162float(h1));
            hi[k] = (uint32_t)__bfloat16_as_ushort(h0) | ((uint32_t)__bfloat16_as_ushort(h1) << 16);
            lo[k] = (uint32_t)__bfloat16_as_ushort(l0) | ((uint32_t)__bfloat16_as_ushort(l1) << 16);
        }
        reinterpret_cast<uint2*>(g_up_hi)[idx] = make_uint2(hi[0], hi[1]);
        reinterpret_cast<uint2*>(g_up_lo)[idx] = make_uint2(lo[0], lo[1]);
    }
}

__global__ void kp_split_downT(const float* __restrict__ down) {
    __shared__ float t[32][33];
    const int bx = blockIdx.x, by = blockIdx.y;
    const int tx = threadIdx.x, ty = threadIdx.y;
    #pragma unroll
    for (int k = 0; k < 4; ++k)
        t[ty + k * 8][tx] = down[(size_t)(by * 32 + ty + k * 8) * IN_DIM + bx * 32 + tx];
    __syncthreads();
    #pragma unroll
    for (int k = 0; k < 4; ++k) {
        int i = bx * 32 + ty + k * 8;
        int r = by * 32 + tx;
        float v = t[tx][ty + k * 8];
        __nv_bfloat16 h = __float2bfloat16(v);
        __nv_bfloat16 l = __float2bfloat16(v - __bfloat162float(h));
        g_dT_hi[(size_t)i * RANK + r] = h;
        g_dT_lo[(size_t)i * RANK + r] = l;
    }
}

// ==================== k2: mma.sync bf16 split GEMM + fused epilogue ====================
// grid(64 i-tiles[N=64], 86 o-tiles[M=128]), 128 threads = 4 warps (2m x 2n),
// warp tile 64x32. Fragments (a_hi,a_lo,b_hi,b_lo) loaded ONCE per k-step,
// 3 passes (hi*hi + lo*hi + hi*lo) issued from registers into shared accumulators.
#define OFF_AH 0
#define OFF_AL 32768
#define OFF_BH 65536
#define OFF_BL 81920
#define K2_SMEM 98304

__global__ __launch_bounds__(128) void k2_mma(
    const int* __restrict__ weight,
    const float* __restrict__ scale,
    const float* __restrict__ zp)
{
    extern __shared__ __align__(1024) char smem[];
    __shared__ int s_rmax[128];
    const uint32_t sb = smem_to_u32(smem);
    const int tid = threadIdx.x;
    const int wid = tid >> 5;
    const int lane = tid & 31;
    const int i0 = blockIdx.x * 64;
    const int o0 = blockIdx.y * 128;

    s_rmax[tid] = 0;

    // ---- stage A (up o-tile, hi+lo): 128 rows x 256B, swizzled ----
    #pragma unroll
    for (int j = 0; j < 16; ++j) {
        int idx = tid + j * 128;
        int row = idx >> 4;
        int ch = idx & 15;
        uint32_t dst = swz((uint32_t)(row * 256 + ch * 16));
        size_t src = (size_t)(o0 + row) * 256 + ch * 16;
        *reinterpret_cast<uint4*>(smem + OFF_AH + dst) =
            *reinterpret_cast<const uint4*>(reinterpret_cast<const char*>(g_up_hi) + src);
        *reinterpret_cast<uint4*>(smem + OFF_AL + dst) =
            *reinterpret_cast<const uint4*>(reinterpret_cast<const char*>(g_up_lo) + src);
    }
    // ---- stage B (downT i-tile, hi+lo): 64 rows x 256B ----
    #pragma unroll
    for (int j = 0; j < 8; ++j) {
        int idx = tid + j * 128;
        int row = idx >> 4;
        int ch = idx & 15;
        uint32_t dst = swz((uint32_t)(row * 256 + ch * 16));
        size_t src = (size_t)(i0 + row) * 256 + ch * 16;
        *reinterpret_cast<uint4*>(smem + OFF_BH + dst) =
            *reinterpret_cast<const uint4*>(reinterpret_cast<const char*>(g_dT_hi) + src);
        *reinterpret_cast<uint4*>(smem + OFF_BL + dst) =
            *reinterpret_cast<const uint4*>(reinterpret_cast<const char*>(g_dT_lo) + src);
    }
    __syncthreads();

    const int wm = (wid & 1) * 64;   // warp m-base (o rows): warp covers 64 rows
    const int wn = (wid >> 1) * 32;  // warp n-base (i cols): warp covers 32 cols

    float c[4][4][4];                // [mi 16-row tiles][ni 8-col tiles][frag]
    #pragma unroll
    for (int mi = 0; mi < 4; ++mi)
        #pragma unroll
        for (int ni = 0; ni < 4; ++ni)
            #pragma unroll
            for (int q = 0; q < 4; ++q) c[mi][ni][q] = 0.f;

    const int a_row = (lane & 15);
    const int a_ch  = (lane >> 4);
    const int b_row = (lane & 7) + ((lane >> 4) << 3);
    const int b_ch  = (lane >> 3) & 1;

    #pragma unroll
    for (int ks = 0; ks < 8; ++ks) {
        uint32_t ah[4][4], al[4][4], bh[2][4], bl[2][4];
        #pragma unroll
        for (int mi = 0; mi < 4; ++mi) {
            uint32_t off = swz((uint32_t)((wm + mi * 16 + a_row) * 256 + (ks * 2 + a_ch) * 16));
            ldsm_x4(ah[mi], sb + OFF_AH + off);
            ldsm_x4(al[mi], sb + OFF_AL + off);
        }
        #pragma unroll
        for (int g = 0; g < 2; ++g) {
            uint32_t off = swz((uint32_t)((wn + g * 16 + b_row) * 256 + (ks * 2 + b_ch) * 16));
            ldsm_x4(bh[g], sb + OFF_BH + off);
            ldsm_x4(bl[g], sb + OFF_BL + off);
        }
        #pragma unroll
        for (int mi = 0; mi < 4; ++mi)
            #pragma unroll
            for (int ni = 0; ni < 4; ++ni) {
                const int g = ni >> 1, h = (ni & 1) * 2;
                mma_bf16(c[mi][ni], ah[mi], bh[g][h], bh[g][h + 1]);   // hi*hi
                mma_bf16(c[mi][ni], al[mi], bh[g][h], bh[g][h + 1]);   // lo*hi
                mma_bf16(c[mi][ni], ah[mi], bl[g][h], bl[g][h + 1]);   // hi*lo
            }
    }

    // ---- fused epilogue: W_f = (w - zp)*scale + D, rowmax, store ----
    const int gq = blockIdx.x >> 1;
    #pragma unroll
    for (int mi = 0; mi < 4; ++mi) {
        #pragma unroll
        for (int half = 0; half < 2; ++half) {
            const int rloc = wm + mi * 16 + (lane >> 2) + half * 8;
            const int o = o0 + rloc;
            const float zpv = zp[o * NG + gq];
            const float scv = scale[o * NG + gq];
            float mx = 0.f;
            #pragma unroll
            for (int ni = 0; ni < 4; ++ni) {
                const int i = i0 + wn + ni * 8 + (lane & 3) * 2;
                int2 w = *reinterpret_cast<const int2*>(&weight[(size_t)o * IN_DIM + i]);
                float v0 = fmaf((float)w.x - zpv, scv, c[mi][ni][half * 2 + 0]);
                float v1 = fmaf((float)w.y - zpv, scv, c[mi][ni][half * 2 + 1]);
                mx = fmaxf(mx, fmaxf(fabsf(v0), fabsf(v1)));
                *reinterpret_cast<float2*>(&g_Wf[(size_t)o * IN_DIM + i]) = make_float2(v0, v1);
            }
            atomicMax(&s_rmax[rloc], __float_as_int(mx));
        }
    }
    __syncthreads();
    atomicMax(&g_rowmax[o0 + tid], s_rmax[tid]);
}

// ==================== k2b: per-row quant multiplier ====================
__global__ void k2b_rowrcp() {
    int o = blockIdx.x * 256 + threadIdx.x;
    if (o < OUT_DIM) {
        float s = __fdiv_rn(__int_as_float(g_rowmax[o]), 127.0f);
        g_rcpw[o] = __frcp_rn(s);
    }
}

// ==================== k3: W quant + dp4a GEMM (K-split x4) ====================
__global__ __launch_bounds__(256) void k3_int8() {
    __shared__ __align__(16) int s_xq[NTOK * 36];
    __shared__ __align__(16) int s_wq[128 * 36];
    __shared__ float s_rcp[128];
    const int o0 = blockIdx.x * 128;
    const int kb = blockIdx.y;
    const int tid = threadIdx.x;
    const int tx = tid & 15;
    const int ty = tid >> 4;
    if (tid < 128) s_rcp[tid] = g_rcpw[o0 + tid];

    int acc[4][8];
    #pragma unroll
    for (int m = 0; m < 4; ++m)
        #pragma unroll
        for (int n = 0; n < 8; ++n) acc[m][n] = 0;

    const int pb = kb * 256;
    for (int c = 0; c < 8; ++c) {
        const int pc = pb + c * 32;
        __syncthreads();
        #pragma unroll
        for (int j = 0; j < 8; ++j) {
            int idx = tid + j * 256;
            int t = idx >> 5, p = idx & 31;
            s_xq[t * 36 + p] = g_xq[t * NPACK + pc + p];
        }
        #pragma unroll
        for (int j = 0; j < 16; ++j) {
            int idx = tid + j * 256;
            int row = idx >> 5, p = idx & 31;
            float4 v = *reinterpret_cast<const float4*>(
                &g_Wf[(size_t)(o0 + row) * IN_DIM + (size_t)(pc + p) * 4]);
            s_wq[row * 36 + p] = quant_pack4_mul(v, s_rcp[row]);
        }
        __syncthreads();

        #pragma unroll
        for (int p4 = 0; p4 < 8; ++p4) {
            int4 a[4];
            #pragma unroll
            for (int m = 0; m < 4; ++m)
                a[m] = *reinterpret_cast<const int4*>(&s_xq[(ty + 16 * m) * 36 + p4 * 4]);
            #pragma unroll
            for (int n = 0; n < 8; ++n) {
                int4 b = *reinterpret_cast<const int4*>(&s_wq[(tx + 16 * n) * 36 + p4 * 4]);
                #pragma unroll
                for (int m = 0; m < 4; ++m) {
                    acc[m][n] = dp4a_s32(a[m].x, b.x, acc[m][n]);
                    acc[m][n] = dp4a_s32(a[m].y, b.y, acc[m][n]);
                    acc[m][n] = dp4a_s32(a[m].z, b.z, acc[m][n]);
                    acc[m][n] = dp4a_s32(a[m].w, b.w, acc[m][n]);
                }
            }
        }
    }

    #pragma unroll
    for (int m = 0; m < 4; ++m) {
        int t = ty + 16 * m;
        #pragma unroll
        for (int n = 0; n < 8; ++n)
            g_part[kb][t * OUT_DIM + o0 + tx + 16 * n] = acc[m][n];
    }
}

// ==================== k4: combine partials + epilogue ====================
__global__ void k4_out(const float* __restrict__ bias, float* __restrict__ out) {
    int o = blockIdx.x * 256 + threadIdx.x;
    int t = blockIdx.y;
    if (o < OUT_DIM) {
        int s = g_part[0][t * OUT_DIM + o] + g_part[1][t * OUT_DIM + o]
              + g_part[2][t * OUT_DIM + o] + g_part[3][t * OUT_DIM + o];
        float sw = __fdiv_rn(__int_as_float(g_rowmax[o]), 127.0f);
        out[(size_t)t * OUT_DIM + o] = ((float)s * g_scale_x[t]) * sw + bias[o];
    }
}

// ==================== launch ====================
extern "C" void kernel_launch(void* const* d_in, const int* in_sizes, int n_in,
                              void* d_out, int out_size)
{
    const float* x      = (const float*)d_in[0];
    const int*   weight = (const int*)  d_in[1];
    const float* scale  = (const float*)d_in[2];
    const float* zp     = (const float*)d_in[3];
    const float* up     = (const float*)d_in[4];
    const float* down   = (const float*)d_in[5];
    const float* bias   = (const float*)d_in[6];
    float* out = (float*)d_out;

    cudaFuncSetAttribute(k2_mma, cudaFuncAttributeMaxDynamicSharedMemorySize, K2_SMEM);

    k1_quant_x<<<64, 256>>>(x);
    kp_split_up<<<(OUT_DIM * RANK / 4 + 255) / 256, 256>>>(up);
    kp_split_downT<<<dim3(IN_DIM / 32, RANK / 32), dim3(32, 8)>>>(down);
    k2_mma<<<dim3(64, 86), 128, K2_SMEM>>>(weight, scale, zp);
    k2b_rowrcp<<<(OUT_DIM + 255) / 256, 256>>>();
    k3_int8<<<dim3(86, 4), 256>>>();
    k4_out<<<dim3((OUT_DIM + 255) / 256, NTOK), 256>>>(bias, out);
}